// round 1
// baseline (speedup 1.0000x reference)
#include <cuda_runtime.h>
#include <cuda_bf16.h>
#include <math.h>

// Problem dims
#define BB 128
#define TT 128
#define VV 1024
#define EE 512
#define HH 1024
#define GG 4096   // 4*H

// d_out layout (floats): decoder_outputs [B,T,H], hf [B,H], cf [B,H], symbols [B,T]
#define OUT_DEC 0
#define OUT_HF  (BB*TT*HH)            // 16777216
#define OUT_CF  (OUT_HF + BB*HH)      // 16908288
#define OUT_SYM (OUT_CF + BB*HH)      // 17039360

// ---------------- scratch (static device memory; no allocation) ----------------
__device__ float g_dec_table[VV * GG];      // emb @ dec_W_ih^T + dec_b   (16.8 MB)
__device__ float g_pregates_enc[TT * GG];   // row-127 enc input pregates (2 MB)
__device__ float g_he[2][HH];               // encoder h double buffer (row 127 only)
__device__ float g_ce[HH];                  // encoder c
__device__ float g_hd[2][BB * HH];          // decoder h double buffer
__device__ float g_cd[BB * HH];             // decoder c
__device__ int   g_sym[BB];                 // current decoder symbols
__device__ float g_fc_part[4][BB * HH];     // fc K-split partials (2 MB)
__device__ int   g_idx64;                   // 1 if inputs buffer is int64

// ---------------- helpers ----------------
__device__ __forceinline__ int read_idx(const void* p, int i) {
    if (g_idx64) return (int)((const long long*)p)[i];
    return ((const int*)p)[i];
}
__device__ __forceinline__ float sigf(float x) { return 1.0f / (1.0f + expf(-x)); }

// Detect input index dtype (int64 values are all < 1024 => high words zero)
__global__ void detect_kernel(const void* p) {
    if (threadIdx.x == 0) {
        const unsigned long long* q = (const unsigned long long*)p;
        int ok = 1;
        for (int i = 0; i < 8; i++) if (q[i] > 1023ull) ok = 0;
        g_idx64 = ok;
    }
}

// ---------------- table GEMM: C[m][g] = sum_k A[row(m)][k]*W[g][k] + bias[g] ----------------
// Tile 64x64, 256 threads, 4x4 per thread, KC=16. K=512. C stride = 4096.
__device__ __forceinline__ void table_gemm_body(
    const float* __restrict__ A, const float* __restrict__ W,
    const float* __restrict__ bias, float* __restrict__ C,
    int K, const void* map, int map_off)
{
    __shared__ float Ash[16][68];
    __shared__ float Bsh[16][68];
    int tid = threadIdx.x;
    int tm = tid & 15, tn = tid >> 4;
    int n0 = blockIdx.x * 64, m0 = blockIdx.y * 64;

    int r  = tid >> 2;          // 0..63
    int kf = (tid & 3) << 2;    // 0,4,8,12
    int am = m0 + r;
    int arow = am;
    if (map) arow = read_idx(map, map_off + am);
    const float* Aptr = A + (size_t)arow * K;
    const float* Wptr = W + (size_t)(n0 + r) * K;

    float acc[4][4] = {};
    for (int k0 = 0; k0 < K; k0 += 16) {
        float4 av = *(const float4*)(Aptr + k0 + kf);
        float4 bv = *(const float4*)(Wptr + k0 + kf);
        __syncthreads();
        Ash[kf+0][r] = av.x; Ash[kf+1][r] = av.y; Ash[kf+2][r] = av.z; Ash[kf+3][r] = av.w;
        Bsh[kf+0][r] = bv.x; Bsh[kf+1][r] = bv.y; Bsh[kf+2][r] = bv.z; Bsh[kf+3][r] = bv.w;
        __syncthreads();
#pragma unroll
        for (int k = 0; k < 16; k++) {
            float4 a4 = *(const float4*)&Ash[k][tm * 4];
            float4 b4 = *(const float4*)&Bsh[k][tn * 4];
            acc[0][0] += a4.x * b4.x; acc[0][1] += a4.x * b4.y; acc[0][2] += a4.x * b4.z; acc[0][3] += a4.x * b4.w;
            acc[1][0] += a4.y * b4.x; acc[1][1] += a4.y * b4.y; acc[1][2] += a4.y * b4.z; acc[1][3] += a4.y * b4.w;
            acc[2][0] += a4.z * b4.x; acc[2][1] += a4.z * b4.y; acc[2][2] += a4.z * b4.z; acc[2][3] += a4.z * b4.w;
            acc[3][0] += a4.w * b4.x; acc[3][1] += a4.w * b4.y; acc[3][2] += a4.w * b4.z; acc[3][3] += a4.w * b4.w;
        }
    }
#pragma unroll
    for (int i = 0; i < 4; i++) {
        int m = m0 + tm * 4 + i;
#pragma unroll
        for (int j = 0; j < 4; j++) {
            int n = n0 + tn * 4 + j;
            C[(size_t)m * GG + n] = acc[i][j] + bias[n];
        }
    }
}

__global__ __launch_bounds__(256) void table_dec_kernel(
    const float* __restrict__ emb, const float* __restrict__ W, const float* __restrict__ bias)
{
    table_gemm_body(emb, W, bias, g_dec_table, EE, nullptr, 0);
}
__global__ __launch_bounds__(256) void table_pre_kernel(
    const float* __restrict__ emb, const float* __restrict__ W, const float* __restrict__ bias,
    const void* __restrict__ inputs)
{
    table_gemm_body(emb, W, bias, g_pregates_enc, EE, inputs, 127 * TT);
}

// ---------------- encoder (batch row 127 only) ----------------
__global__ void enc_init_kernel() {
    int i = blockIdx.x * 256 + threadIdx.x;
    if (i < HH) { g_he[0][i] = 0.0f; g_ce[i] = 0.0f; }
}

// one step: grid 128 CTAs x 256 threads; warp computes 4 gate dots for one j
__global__ __launch_bounds__(256) void enc_step_kernel(int t, const float* __restrict__ Whh) {
    int wid = threadIdx.x >> 5, lane = threadIdx.x & 31;
    int j = blockIdx.x * 8 + wid;
    const float* hin = g_he[t & 1];
    const float* w = Whh + (size_t)j * HH;
    float a0 = 0.f, a1 = 0.f, a2 = 0.f, a3 = 0.f;
#pragma unroll 4
    for (int k = lane; k < HH; k += 32) {
        float hv = hin[k];
        a0 += hv * w[k];
        a1 += hv * w[1024 * 1024 + k];
        a2 += hv * w[2 * 1024 * 1024 + k];
        a3 += hv * w[3 * 1024 * 1024 + k];
    }
#pragma unroll
    for (int o = 16; o; o >>= 1) {
        a0 += __shfl_xor_sync(0xffffffffu, a0, o);
        a1 += __shfl_xor_sync(0xffffffffu, a1, o);
        a2 += __shfl_xor_sync(0xffffffffu, a2, o);
        a3 += __shfl_xor_sync(0xffffffffu, a3, o);
    }
    if (lane == 0) {
        const float* pg = g_pregates_enc + (size_t)t * GG;
        float gi = a0 + pg[j];
        float gf = a1 + pg[HH + j];
        float gg = a2 + pg[2 * HH + j];
        float go = a3 + pg[3 * HH + j];
        float i_ = sigf(gi), f_ = sigf(gf), c_ = tanhf(gg), o_ = sigf(go);
        float c = f_ * g_ce[j] + i_ * c_;
        g_ce[j] = c;
        g_he[(t + 1) & 1][j] = o_ * tanhf(c);
    }
}

// ---------------- decoder ----------------
__global__ void dec_init_kernel(const void* __restrict__ inputs) {
    int i = blockIdx.x * 256 + threadIdx.x;   // 0..131071
    int b = i >> 10, k = i & 1023;
    g_hd[0][i] = (b == 127) ? g_he[0][k] : 0.0f;
    g_cd[i]    = (b == 127) ? g_ce[k]    : 0.0f;
    if (i < BB) g_sym[i] = read_idx(inputs, i * TT);
}

// gates = dec_table[sym] + h @ W_hh^T, fused LSTM epilogue.
// grid (32 j-tiles, 4 b-tiles), 256 threads. CTA: 32 b x 32 j x 4 gates, K=1024.
__global__ __launch_bounds__(256) void dec_gates_kernel(int t, const float* __restrict__ Whh) {
    __shared__ float hsh[32][36];
    __shared__ float wsh[32][132];
    __shared__ int ssym[32];
    int tid = threadIdx.x;
    int tx = tid & 31, ty = tid >> 5;
    int j0 = blockIdx.x * 32, b0 = blockIdx.y * 32;
    const float* hin = g_hd[t & 1];
    float* hout = g_hd[(t + 1) & 1];
    if (tid < 32) ssym[tid] = g_sym[b0 + tid];

    int lb = tid >> 3;          // 0..31
    int kf = (tid & 7) << 2;    // 0..28
    float acc[4][4] = {};

    for (int k0 = 0; k0 < HH; k0 += 32) {
        float4 hv = *(const float4*)(hin + (size_t)(b0 + lb) * HH + k0 + kf);
        float4 wv[4];
#pragma unroll
        for (int rep = 0; rep < 4; rep++) {
            int u = tid + rep * 256;
            int r = u >> 3; int kf2 = (u & 7) << 2;
            int q = r >> 5, jj = r & 31;
            wv[rep] = *(const float4*)(Whh + (size_t)(q * HH + j0 + jj) * HH + k0 + kf2);
        }
        __syncthreads();
        hsh[kf + 0][lb] = hv.x; hsh[kf + 1][lb] = hv.y; hsh[kf + 2][lb] = hv.z; hsh[kf + 3][lb] = hv.w;
#pragma unroll
        for (int rep = 0; rep < 4; rep++) {
            int u = tid + rep * 256;
            int r = u >> 3; int kf2 = (u & 7) << 2;
            wsh[kf2 + 0][r] = wv[rep].x; wsh[kf2 + 1][r] = wv[rep].y;
            wsh[kf2 + 2][r] = wv[rep].z; wsh[kf2 + 3][r] = wv[rep].w;
        }
        __syncthreads();
#pragma unroll
        for (int k = 0; k < 32; k++) {
            float4 h4 = *(const float4*)&hsh[k][ty * 4];
            float w0 = wsh[k][tx], w1 = wsh[k][32 + tx], w2 = wsh[k][64 + tx], w3 = wsh[k][96 + tx];
            acc[0][0] += h4.x * w0; acc[0][1] += h4.y * w0; acc[0][2] += h4.z * w0; acc[0][3] += h4.w * w0;
            acc[1][0] += h4.x * w1; acc[1][1] += h4.y * w1; acc[1][2] += h4.z * w1; acc[1][3] += h4.w * w1;
            acc[2][0] += h4.x * w2; acc[2][1] += h4.y * w2; acc[2][2] += h4.z * w2; acc[2][3] += h4.w * w2;
            acc[3][0] += h4.x * w3; acc[3][1] += h4.y * w3; acc[3][2] += h4.z * w3; acc[3][3] += h4.w * w3;
        }
    }

    int jg = j0 + tx;
#pragma unroll
    for (int i = 0; i < 4; i++) {
        int b = b0 + ty * 4 + i;
        int s = ssym[ty * 4 + i];
        const float* tb = g_dec_table + (size_t)s * GG + jg;
        float gi = acc[0][i] + tb[0];
        float gf = acc[1][i] + tb[HH];
        float gg = acc[2][i] + tb[2 * HH];
        float go = acc[3][i] + tb[3 * HH];
        float i_ = sigf(gi), f_ = sigf(gf), c_ = tanhf(gg), o_ = sigf(go);
        int off = b * HH + jg;
        float c = f_ * g_cd[off] + i_ * c_;
        g_cd[off] = c;
        hout[off] = o_ * tanhf(c);
    }
}

// fc partials: out_part[s][b][n] = sum_{k in split s} h[b][k]*fc_W[n][k]
// grid (32 n-tiles, 4 b-tiles, 4 k-splits), 256 threads, tile 32b x 32n, K chunk 256.
__global__ __launch_bounds__(256) void fc_part_kernel(int t, const float* __restrict__ fcW) {
    __shared__ float hsh[32][36];
    __shared__ float wsh[32][36];
    int tid = threadIdx.x;
    int tx = tid & 31, ty = tid >> 5;
    int n0 = blockIdx.x * 32, b0 = blockIdx.y * 32, ks = blockIdx.z;
    const float* h = g_hd[(t + 1) & 1];
    int lb = tid >> 3;
    int kf = (tid & 7) << 2;
    float acc[4] = {};
    for (int kc = 0; kc < 8; kc++) {
        int k0 = ks * 256 + kc * 32;
        float4 hv = *(const float4*)(h   + (size_t)(b0 + lb) * HH + k0 + kf);
        float4 wv = *(const float4*)(fcW + (size_t)(n0 + lb) * HH + k0 + kf);
        __syncthreads();
        hsh[kf + 0][lb] = hv.x; hsh[kf + 1][lb] = hv.y; hsh[kf + 2][lb] = hv.z; hsh[kf + 3][lb] = hv.w;
        wsh[kf + 0][lb] = wv.x; wsh[kf + 1][lb] = wv.y; wsh[kf + 2][lb] = wv.z; wsh[kf + 3][lb] = wv.w;
        __syncthreads();
#pragma unroll
        for (int k = 0; k < 32; k++) {
            float4 h4 = *(const float4*)&hsh[k][ty * 4];
            float w = wsh[k][tx];
            acc[0] += h4.x * w; acc[1] += h4.y * w; acc[2] += h4.z * w; acc[3] += h4.w * w;
        }
    }
#pragma unroll
    for (int i = 0; i < 4; i++)
        g_fc_part[ks][(b0 + ty * 4 + i) * HH + n0 + tx] = acc[i];
}

// combine partials + bias, write logits to d_out, argmax (JAX first-max semantics)
__global__ __launch_bounds__(256) void fc_comb_kernel(int t, const float* __restrict__ fcb,
                                                      float* __restrict__ out) {
    __shared__ float sv[256];
    __shared__ int   si[256];
    int b = blockIdx.x;
    int tid = threadIdx.x;
    float best = -INFINITY; int bi = 0;
    float* orow = out + OUT_DEC + (size_t)b * TT * HH + (size_t)t * HH;
#pragma unroll
    for (int rep = 0; rep < 4; rep++) {
        int n = tid + rep * 256;
        float v = g_fc_part[0][b * HH + n] + g_fc_part[1][b * HH + n]
                + g_fc_part[2][b * HH + n] + g_fc_part[3][b * HH + n] + fcb[n];
        orow[n] = v;
        if (v > best || (v == best && n < bi)) { best = v; bi = n; }
    }
    sv[tid] = best; si[tid] = bi;
    __syncthreads();
    for (int s = 128; s; s >>= 1) {
        if (tid < s) {
            float ov = sv[tid + s]; int oi = si[tid + s];
            if (ov > sv[tid] || (ov == sv[tid] && oi < si[tid])) { sv[tid] = ov; si[tid] = oi; }
        }
        __syncthreads();
    }
    if (tid == 0) {
        g_sym[b] = si[0];
        out[OUT_SYM + b * TT + t] = (float)si[0];
    }
}

__global__ void final_copy_kernel(float* __restrict__ out) {
    int i = blockIdx.x * 256 + threadIdx.x;   // 0..131071
    out[OUT_HF + i] = g_hd[0][i];   // t=127 wrote buffer (128)&1 = 0
    out[OUT_CF + i] = g_cd[i];
}

// ---------------- launcher ----------------
extern "C" void kernel_launch(void* const* d_in, const int* in_sizes, int n_in,
                              void* d_out, int out_size) {
    const void*  inputs = d_in[0];
    const float* emb    = (const float*)d_in[1];
    const float* eWih   = (const float*)d_in[2];
    const float* eWhh   = (const float*)d_in[3];
    const float* eb     = (const float*)d_in[4];
    const float* dWih   = (const float*)d_in[5];
    const float* dWhh   = (const float*)d_in[6];
    const float* db     = (const float*)d_in[7];
    const float* fcW    = (const float*)d_in[8];
    const float* fcb    = (const float*)d_in[9];
    float* out = (float*)d_out;

    detect_kernel<<<1, 32>>>(inputs);

    // one-time tables
    table_dec_kernel<<<dim3(64, 16), 256>>>(emb, dWih, db);
    table_pre_kernel<<<dim3(64, 2), 256>>>(emb, eWih, eb, inputs);

    // encoder (row 127 only)
    enc_init_kernel<<<4, 256>>>();
    for (int t = 0; t < TT; t++)
        enc_step_kernel<<<128, 256>>>(t, eWhh);

    // decoder
    dec_init_kernel<<<512, 256>>>(inputs);
    for (int t = 0; t < TT; t++) {
        dec_gates_kernel<<<dim3(32, 4), 256>>>(t, dWhh);
        fc_part_kernel<<<dim3(32, 4, 4), 256>>>(t, fcW);
        fc_comb_kernel<<<128, 256>>>(t, fcb, out);
    }
    final_copy_kernel<<<512, 256>>>(out);
}

// round 2
// speedup vs baseline: 1.1019x; 1.1019x over previous
#include <cuda_runtime.h>
#include <cuda_bf16.h>
#include <math.h>

// Problem dims
#define BB 128
#define TT 128
#define VV 1024
#define EE 512
#define HH 1024
#define GG 4096   // 4*H

// d_out layout (floats): decoder_outputs [B,T,H], hf [B,H], cf [B,H], symbols [B,T]
#define OUT_DEC 0
#define OUT_HF  (BB*TT*HH)
#define OUT_CF  (OUT_HF + BB*HH)
#define OUT_SYM (OUT_CF + BB*HH)

#define NCTA 128

// ---------------- scratch (static device memory) ----------------
__device__ float g_dec_table[VV * GG];      // emb @ dec_W_ih^T + dec_b
__device__ float g_pregates_enc[TT * GG];   // row-127 enc input pregates
__device__ float g_he[2][HH];
__device__ float g_ce[HH];
__device__ float g_hd[2][BB * HH];
__device__ float g_cd[BB * HH];
__device__ unsigned long long g_amax[2][BB];
__device__ int   g_idx64;
__device__ unsigned g_bar_count = 0;
__device__ volatile unsigned g_bar_gen = 0;

// ---------------- helpers ----------------
__device__ __forceinline__ int read_idx(const void* p, int i) {
    if (g_idx64) return (int)((const long long*)p)[i];
    return ((const int*)p)[i];
}
__device__ __forceinline__ float sigf(float x) { return 1.0f / (1.0f + expf(-x)); }

__device__ __forceinline__ void ffma2(unsigned long long& d, unsigned long long a, unsigned long long b) {
    asm("fma.rn.f32x2 %0, %1, %2, %0;" : "+l"(d) : "l"(a), "l"(b));
}
__device__ __forceinline__ unsigned long long dupf(float x) {
    unsigned long long r; unsigned u = __float_as_uint(x);
    asm("mov.b64 %0, {%1, %1};" : "=l"(r) : "r"(u));
    return r;
}
__device__ __forceinline__ float lo2(unsigned long long p) { return __uint_as_float((unsigned)p); }
__device__ __forceinline__ float hi2(unsigned long long p) { return __uint_as_float((unsigned)(p >> 32)); }
__device__ __forceinline__ float pick2(const unsigned long long* a2, int i) {
    unsigned long long p = a2[i >> 1];
    return (i & 1) ? hi2(p) : lo2(p);
}
__device__ __forceinline__ unsigned monof(float v) {
    unsigned b = __float_as_uint(v);
    return b ^ ((b & 0x80000000u) ? 0xFFFFFFFFu : 0x80000000u);
}

// grid barrier (all 128 CTAs guaranteed resident: 128 <= 148 SMs, 1 CTA/SM)
__device__ __forceinline__ void grid_bar() {
    __syncthreads();
    if (threadIdx.x == 0) {
        unsigned gen = g_bar_gen;
        __threadfence();
        if (atomicAdd(&g_bar_count, 1) == NCTA - 1) {
            g_bar_count = 0;
            __threadfence();
            g_bar_gen = gen + 1;
        } else {
            while (g_bar_gen == gen) {}
        }
        __threadfence();
    }
    __syncthreads();
}

// Detect input index dtype
__global__ void detect_kernel(const void* p) {
    if (threadIdx.x == 0) {
        const unsigned long long* q = (const unsigned long long*)p;
        int ok = 1;
        for (int i = 0; i < 8; i++) if (q[i] > 1023ull) ok = 0;
        g_idx64 = ok;
    }
}

// ---------------- table GEMM (one-time): C[m][g] = sum_k A[row(m)][k]*W[g][k] + bias[g] ----------------
__device__ __forceinline__ void table_gemm_body(
    const float* __restrict__ A, const float* __restrict__ W,
    const float* __restrict__ bias, float* __restrict__ C,
    int K, const void* map, int map_off)
{
    __shared__ float Ash[16][68];
    __shared__ float Bsh[16][68];
    int tid = threadIdx.x;
    int tm = tid & 15, tn = tid >> 4;
    int n0 = blockIdx.x * 64, m0 = blockIdx.y * 64;

    int r  = tid >> 2;
    int kf = (tid & 3) << 2;
    int am = m0 + r;
    int arow = am;
    if (map) arow = read_idx(map, map_off + am);
    const float* Aptr = A + (size_t)arow * K;
    const float* Wptr = W + (size_t)(n0 + r) * K;

    float acc[4][4] = {};
    for (int k0 = 0; k0 < K; k0 += 16) {
        float4 av = *(const float4*)(Aptr + k0 + kf);
        float4 bv = *(const float4*)(Wptr + k0 + kf);
        __syncthreads();
        Ash[kf+0][r] = av.x; Ash[kf+1][r] = av.y; Ash[kf+2][r] = av.z; Ash[kf+3][r] = av.w;
        Bsh[kf+0][r] = bv.x; Bsh[kf+1][r] = bv.y; Bsh[kf+2][r] = bv.z; Bsh[kf+3][r] = bv.w;
        __syncthreads();
#pragma unroll
        for (int k = 0; k < 16; k++) {
            float4 a4 = *(const float4*)&Ash[k][tm * 4];
            float4 b4 = *(const float4*)&Bsh[k][tn * 4];
            acc[0][0] += a4.x * b4.x; acc[0][1] += a4.x * b4.y; acc[0][2] += a4.x * b4.z; acc[0][3] += a4.x * b4.w;
            acc[1][0] += a4.y * b4.x; acc[1][1] += a4.y * b4.y; acc[1][2] += a4.y * b4.z; acc[1][3] += a4.y * b4.w;
            acc[2][0] += a4.z * b4.x; acc[2][1] += a4.z * b4.y; acc[2][2] += a4.z * b4.z; acc[2][3] += a4.z * b4.w;
            acc[3][0] += a4.w * b4.x; acc[3][1] += a4.w * b4.y; acc[3][2] += a4.w * b4.z; acc[3][3] += a4.w * b4.w;
        }
    }
#pragma unroll
    for (int i = 0; i < 4; i++) {
        int m = m0 + tm * 4 + i;
#pragma unroll
        for (int j = 0; j < 4; j++) {
            int n = n0 + tn * 4 + j;
            C[(size_t)m * GG + n] = acc[i][j] + bias[n];
        }
    }
}

__global__ __launch_bounds__(256) void table_dec_kernel(
    const float* __restrict__ emb, const float* __restrict__ W, const float* __restrict__ bias)
{
    table_gemm_body(emb, W, bias, g_dec_table, EE, nullptr, 0);
}
__global__ __launch_bounds__(256) void table_pre_kernel(
    const float* __restrict__ emb, const float* __restrict__ W, const float* __restrict__ bias,
    const void* __restrict__ inputs)
{
    table_gemm_body(emb, W, bias, g_pregates_enc, EE, inputs, 127 * TT);
}

// ---------------- persistent main kernel: encoder + decoder + fc + argmax ----------------
struct GatesSmem {
    __align__(16) float hsh[32][36];
    float wsh[32][132];
    int ssym[32];
};
struct FcSmem {
    __align__(16) float hsh[32][36];
    float wsh[32][36];
};
union MainSmem { GatesSmem g; FcSmem f; };

__global__ __launch_bounds__(256, 1) void main_kernel(
    const void* __restrict__ inputs,
    const float* __restrict__ eWhh,
    const float* __restrict__ dWhh,
    const float* __restrict__ fcW,
    const float* __restrict__ fcb,
    float* __restrict__ out)
{
    __shared__ MainSmem smem;
    const int cta = blockIdx.x;
    const int tid = threadIdx.x;

    // ---- phase 0: zero encoder state ----
    if (cta == 0) {
        for (int i = tid; i < HH; i += 256) { g_he[0][i] = 0.0f; g_ce[i] = 0.0f; }
    }
    grid_bar();

    // ---- encoder: batch row 127 only, 128 steps ----
    {
        const int wid = tid >> 5, lane = tid & 31;
        const int j = cta * 8 + wid;
        const float* w = eWhh + (size_t)j * HH;
        for (int t = 0; t < TT; t++) {
            const float* hin = g_he[t & 1];
            float a0 = 0.f, a1 = 0.f, a2 = 0.f, a3 = 0.f;
#pragma unroll 4
            for (int k = lane; k < HH; k += 32) {
                float hv = hin[k];
                a0 += hv * w[k];
                a1 += hv * w[1024 * 1024 + k];
                a2 += hv * w[2 * 1024 * 1024 + k];
                a3 += hv * w[3 * 1024 * 1024 + k];
            }
#pragma unroll
            for (int o = 16; o; o >>= 1) {
                a0 += __shfl_xor_sync(0xffffffffu, a0, o);
                a1 += __shfl_xor_sync(0xffffffffu, a1, o);
                a2 += __shfl_xor_sync(0xffffffffu, a2, o);
                a3 += __shfl_xor_sync(0xffffffffu, a3, o);
            }
            if (lane == 0) {
                const float* pg = g_pregates_enc + (size_t)t * GG;
                float gi = a0 + pg[j];
                float gf = a1 + pg[HH + j];
                float gg = a2 + pg[2 * HH + j];
                float go = a3 + pg[3 * HH + j];
                float i_ = sigf(gi), f_ = sigf(gf), c_ = tanhf(gg), o_ = sigf(go);
                float c = f_ * g_ce[j] + i_ * c_;
                g_ce[j] = c;
                g_he[(t + 1) & 1][j] = o_ * tanhf(c);
            }
            grid_bar();
        }
    }

    // ---- decoder init: dh/dc (only batch row 127 gets encoder state) ----
    {
        int base = cta * 1024 + tid * 4;
#pragma unroll
        for (int q = 0; q < 4; q++) {
            int k = tid * 4 + q;
            g_hd[0][base + q] = (cta == 127) ? g_he[0][k] : 0.0f;   // enc final h in buf 0
            g_cd[base + q]    = (cta == 127) ? g_ce[k]    : 0.0f;
        }
    }
    grid_bar();

    // ---- decoder: 128 steps, two phases per step ----
    const int tx = tid & 31, ty = tid >> 5;
    const int lb = tid >> 3, kf = (tid & 7) << 2;
    const int j0 = (cta & 31) * 32;          // gates j-tile / fc n-tile
    const int b0 = (cta >> 5) * 32;          // b-tile

    for (int t = 0; t < TT; t++) {
        // ===== gates phase: gates = dec_table[sym] + h @ W_hh^T, LSTM epilogue =====
        {
            const float* hin = g_hd[t & 1];
            float* hout = g_hd[(t + 1) & 1];

            if (tid < 32) {
                int b = b0 + tid;
                int s;
                if (t == 0) {
                    s = read_idx(inputs, b * TT);
                } else {
                    unsigned long long key = g_amax[(t - 1) & 1][b];
                    s = (int)(~(unsigned)key & 1023u);
                    if ((cta & 31) == 0) out[OUT_SYM + b * TT + (t - 1)] = (float)s;
                }
                smem.g.ssym[tid] = s;
            }
            if (cta == 0 && tid < BB) g_amax[t & 1][tid] = 0ull;

            unsigned long long acc[4][2];
#pragma unroll
            for (int g = 0; g < 4; g++) { acc[g][0] = 0ull; acc[g][1] = 0ull; }

            for (int k0 = 0; k0 < HH; k0 += 32) {
                float4 hv = *(const float4*)(hin + (size_t)(b0 + lb) * HH + k0 + kf);
                float4 wv[4];
#pragma unroll
                for (int rep = 0; rep < 4; rep++) {
                    int u = tid + rep * 256;
                    int r = u >> 3; int kf2 = (u & 7) << 2;
                    int q = r >> 5, jj = r & 31;
                    wv[rep] = *(const float4*)(dWhh + (size_t)(q * HH + j0 + jj) * HH + k0 + kf2);
                }
                __syncthreads();
                smem.g.hsh[kf + 0][lb] = hv.x; smem.g.hsh[kf + 1][lb] = hv.y;
                smem.g.hsh[kf + 2][lb] = hv.z; smem.g.hsh[kf + 3][lb] = hv.w;
#pragma unroll
                for (int rep = 0; rep < 4; rep++) {
                    int u = tid + rep * 256;
                    int r = u >> 3; int kf2 = (u & 7) << 2;
                    smem.g.wsh[kf2 + 0][r] = wv[rep].x; smem.g.wsh[kf2 + 1][r] = wv[rep].y;
                    smem.g.wsh[kf2 + 2][r] = wv[rep].z; smem.g.wsh[kf2 + 3][r] = wv[rep].w;
                }
                __syncthreads();
#pragma unroll
                for (int k = 0; k < 32; k++) {
                    ulonglong2 hp = *(const ulonglong2*)&smem.g.hsh[k][ty * 4];  // warp-broadcast
                    unsigned long long w0 = dupf(smem.g.wsh[k][tx]);
                    unsigned long long w1 = dupf(smem.g.wsh[k][32 + tx]);
                    unsigned long long w2 = dupf(smem.g.wsh[k][64 + tx]);
                    unsigned long long w3 = dupf(smem.g.wsh[k][96 + tx]);
                    ffma2(acc[0][0], hp.x, w0); ffma2(acc[0][1], hp.y, w0);
                    ffma2(acc[1][0], hp.x, w1); ffma2(acc[1][1], hp.y, w1);
                    ffma2(acc[2][0], hp.x, w2); ffma2(acc[2][1], hp.y, w2);
                    ffma2(acc[3][0], hp.x, w3); ffma2(acc[3][1], hp.y, w3);
                }
            }

            int jg = j0 + tx;
#pragma unroll
            for (int i = 0; i < 4; i++) {
                int b = b0 + ty * 4 + i;
                int s = smem.g.ssym[ty * 4 + i];
                const float* tb = g_dec_table + (size_t)s * GG + jg;
                float gi = pick2(acc[0], i) + tb[0];
                float gf = pick2(acc[1], i) + tb[HH];
                float gg = pick2(acc[2], i) + tb[2 * HH];
                float go = pick2(acc[3], i) + tb[3 * HH];
                float i_ = sigf(gi), f_ = sigf(gf), c_ = tanhf(gg), o_ = sigf(go);
                int off = b * HH + jg;
                float c = f_ * g_cd[off] + i_ * c_;
                g_cd[off] = c;
                hout[off] = o_ * tanhf(c);
            }
        }
        grid_bar();

        // ===== fc phase: logits = h @ fc_W^T + fc_b; write + argmax =====
        {
            const float* h = g_hd[(t + 1) & 1];
            unsigned long long acc[2] = {0ull, 0ull};

            for (int k0 = 0; k0 < HH; k0 += 32) {
                float4 hv = *(const float4*)(h   + (size_t)(b0 + lb) * HH + k0 + kf);
                float4 wv = *(const float4*)(fcW + (size_t)(j0 + lb) * HH + k0 + kf);
                __syncthreads();
                smem.f.hsh[kf + 0][lb] = hv.x; smem.f.hsh[kf + 1][lb] = hv.y;
                smem.f.hsh[kf + 2][lb] = hv.z; smem.f.hsh[kf + 3][lb] = hv.w;
                smem.f.wsh[kf + 0][lb] = wv.x; smem.f.wsh[kf + 1][lb] = wv.y;
                smem.f.wsh[kf + 2][lb] = wv.z; smem.f.wsh[kf + 3][lb] = wv.w;
                __syncthreads();
#pragma unroll
                for (int k = 0; k < 32; k++) {
                    ulonglong2 hp = *(const ulonglong2*)&smem.f.hsh[k][ty * 4];
                    unsigned long long w = dupf(smem.f.wsh[k][tx]);
                    ffma2(acc[0], hp.x, w);
                    ffma2(acc[1], hp.y, w);
                }
            }

            int n = j0 + tx;
            float bias = fcb[n];
            float v[4] = { lo2(acc[0]) + bias, hi2(acc[0]) + bias,
                           lo2(acc[1]) + bias, hi2(acc[1]) + bias };
#pragma unroll
            for (int i = 0; i < 4; i++) {
                int b = b0 + ty * 4 + i;
                out[OUT_DEC + (size_t)b * TT * HH + (size_t)t * HH + n] = v[i];
            }
            // per-warp argmax (lanes = 32 n's of one n-tile) + packed atomicMax
#pragma unroll
            for (int i = 0; i < 4; i++) {
                unsigned long long key =
                    ((unsigned long long)monof(v[i]) << 32) | (unsigned)(~(unsigned)n);
#pragma unroll
                for (int off = 16; off; off >>= 1) {
                    unsigned long long o = __shfl_xor_sync(0xffffffffu, key, off);
                    if (o > key) key = o;
                }
                if (tx == 0) atomicMax(&g_amax[t & 1][b0 + ty * 4 + i], key);
            }
        }
        grid_bar();
    }

    // ---- final: symbols for t=127, hf/cf ----
    if ((cta & 31) == 0 && tid < 32) {
        int b = b0 + tid;
        unsigned long long key = g_amax[1][b];   // 127 & 1
        out[OUT_SYM + b * TT + 127] = (float)(~(unsigned)key & 1023u);
    }
    {
        int base = cta * 1024 + tid * 4;
#pragma unroll
        for (int q = 0; q < 4; q++) {
            out[OUT_HF + base + q] = g_hd[0][base + q];   // (127+1)&1 == 0
            out[OUT_CF + base + q] = g_cd[base + q];
        }
    }
}

// ---------------- launcher ----------------
extern "C" void kernel_launch(void* const* d_in, const int* in_sizes, int n_in,
                              void* d_out, int out_size) {
    const void*  inputs = d_in[0];
    const float* emb    = (const float*)d_in[1];
    const float* eWih   = (const float*)d_in[2];
    const float* eWhh   = (const float*)d_in[3];
    const float* eb     = (const float*)d_in[4];
    const float* dWih   = (const float*)d_in[5];
    const float* dWhh   = (const float*)d_in[6];
    const float* db     = (const float*)d_in[7];
    const float* fcW    = (const float*)d_in[8];
    const float* fcb    = (const float*)d_in[9];
    float* out = (float*)d_out;

    detect_kernel<<<1, 32>>>(inputs);
    table_dec_kernel<<<dim3(64, 16), 256>>>(emb, dWih, db);
    table_pre_kernel<<<dim3(64, 2), 256>>>(emb, eWih, eb, inputs);
    main_kernel<<<NCTA, 256>>>(inputs, eWhh, dWhh, fcW, fcb, out);
}

// round 3
// speedup vs baseline: 1.3911x; 1.2625x over previous
#include <cuda_runtime.h>
#include <cuda_bf16.h>
#include <math.h>

// Problem dims
#define BB 128
#define TT 128
#define VV 1024
#define EE 512
#define HH 1024
#define GG 4096   // 4*H

// d_out layout (floats): decoder_outputs [B,T,H], hf [B,H], cf [B,H], symbols [B,T]
#define OUT_DEC 0
#define OUT_HF  (BB*TT*HH)
#define OUT_CF  (OUT_HF + BB*HH)
#define OUT_SYM (OUT_CF + BB*HH)

#define NCTA 128

// ---------------- scratch (static device memory) ----------------
__device__ float g_dec_table[VV * GG];      // emb @ dec_W_ih^T + dec_b
__device__ float g_pregates_enc[TT * GG];   // row-127 enc input pregates
__device__ float g_he[2][HH];
__device__ float g_ce[HH];
__device__ float g_hd[2][BB * HH];          // decoder h, [b][k], double buffered
__device__ float g_cd[BB * HH];             // decoder c, [b][j]
__device__ unsigned long long g_amax[2][BB];
__device__ int   g_idx64;
__device__ unsigned g_bar_count = 0;
__device__ unsigned g_bar_gen = 0;

// ---------------- helpers ----------------
__device__ __forceinline__ int read_idx(const void* p, int i) {
    if (g_idx64) return (int)((const long long*)p)[i];
    return ((const int*)p)[i];
}
__device__ __forceinline__ float sigf(float x) { return 1.0f / (1.0f + expf(-x)); }

__device__ __forceinline__ void ffma2(unsigned long long& d, unsigned long long a, unsigned long long b) {
    asm("fma.rn.f32x2 %0, %1, %2, %0;" : "+l"(d) : "l"(a), "l"(b));
}
__device__ __forceinline__ unsigned long long dupf(float x) {
    unsigned long long r; unsigned u = __float_as_uint(x);
    asm("mov.b64 %0, {%1, %1};" : "=l"(r) : "r"(u));
    return r;
}
__device__ __forceinline__ float lo2(unsigned long long p) { return __uint_as_float((unsigned)p); }
__device__ __forceinline__ float hi2(unsigned long long p) { return __uint_as_float((unsigned)(p >> 32)); }
__device__ __forceinline__ unsigned monof(float v) {
    unsigned b = __float_as_uint(v);
    return b ^ ((b & 0x80000000u) ? 0xFFFFFFFFu : 0x80000000u);
}

// grid barrier: release/acquire gpu scope (all 128 CTAs resident: 1 per SM)
__device__ __forceinline__ void grid_bar() {
    __syncthreads();
    if (threadIdx.x == 0) {
        unsigned gen;
        asm volatile("ld.acquire.gpu.u32 %0, [%1];" : "=r"(gen) : "l"(&g_bar_gen));
        unsigned old;
        asm volatile("atom.add.release.gpu.u32 %0, [%1], 1;" : "=r"(old) : "l"(&g_bar_count));
        if (old == NCTA - 1) {
            g_bar_count = 0;
            asm volatile("st.release.gpu.u32 [%0], %1;" :: "l"(&g_bar_gen), "r"(gen + 1));
        } else {
            unsigned cur;
            do {
                asm volatile("ld.acquire.gpu.u32 %0, [%1];" : "=r"(cur) : "l"(&g_bar_gen));
            } while (cur == gen);
        }
    }
    __syncthreads();
}

// Detect input index dtype
__global__ void detect_kernel(const void* p) {
    if (threadIdx.x == 0) {
        const unsigned long long* q = (const unsigned long long*)p;
        int ok = 1;
        for (int i = 0; i < 8; i++) if (q[i] > 1023ull) ok = 0;
        g_idx64 = ok;
    }
}

// ---------------- table GEMM (one-time): C[m][g] = sum_k A[row(m)][k]*W[g][k] + bias[g] ----------------
__device__ __forceinline__ void table_gemm_body(
    const float* __restrict__ A, const float* __restrict__ W,
    const float* __restrict__ bias, float* __restrict__ C,
    int K, const void* map, int map_off)
{
    __shared__ __align__(16) float Ash[16][68];
    __shared__ __align__(16) float Bsh[16][68];
    int tid = threadIdx.x;
    int tm = tid & 15, tn = tid >> 4;
    int n0 = blockIdx.x * 64, m0 = blockIdx.y * 64;

    int r  = tid >> 2;
    int kf = (tid & 3) << 2;
    int am = m0 + r;
    int arow = am;
    if (map) arow = read_idx(map, map_off + am);
    const float* Aptr = A + (size_t)arow * K;
    const float* Wptr = W + (size_t)(n0 + r) * K;

    unsigned long long accp[4][2];
#pragma unroll
    for (int i = 0; i < 4; i++) { accp[i][0] = 0ull; accp[i][1] = 0ull; }

    for (int k0 = 0; k0 < K; k0 += 16) {
        float4 av = *(const float4*)(Aptr + k0 + kf);
        float4 bv = *(const float4*)(Wptr + k0 + kf);
        __syncthreads();
        Ash[kf+0][r] = av.x; Ash[kf+1][r] = av.y; Ash[kf+2][r] = av.z; Ash[kf+3][r] = av.w;
        Bsh[kf+0][r] = bv.x; Bsh[kf+1][r] = bv.y; Bsh[kf+2][r] = bv.z; Bsh[kf+3][r] = bv.w;
        __syncthreads();
#pragma unroll
        for (int k = 0; k < 16; k++) {
            float4 a4 = *(const float4*)&Ash[k][tm * 4];
            ulonglong2 b01 = *(const ulonglong2*)&Bsh[k][tn * 4];
            unsigned long long a0 = dupf(a4.x), a1 = dupf(a4.y), a2 = dupf(a4.z), a3 = dupf(a4.w);
            ffma2(accp[0][0], b01.x, a0); ffma2(accp[0][1], b01.y, a0);
            ffma2(accp[1][0], b01.x, a1); ffma2(accp[1][1], b01.y, a1);
            ffma2(accp[2][0], b01.x, a2); ffma2(accp[2][1], b01.y, a2);
            ffma2(accp[3][0], b01.x, a3); ffma2(accp[3][1], b01.y, a3);
        }
    }
#pragma unroll
    for (int i = 0; i < 4; i++) {
        int m = m0 + tm * 4 + i;
#pragma unroll
        for (int p = 0; p < 2; p++) {
            int n = n0 + tn * 4 + p * 2;
            C[(size_t)m * GG + n]     = lo2(accp[i][p]) + bias[n];
            C[(size_t)m * GG + n + 1] = hi2(accp[i][p]) + bias[n + 1];
        }
    }
}

__global__ __launch_bounds__(256) void table_dec_kernel(
    const float* __restrict__ emb, const float* __restrict__ W, const float* __restrict__ bias)
{
    table_gemm_body(emb, W, bias, g_dec_table, EE, nullptr, 0);
}
__global__ __launch_bounds__(256) void table_pre_kernel(
    const float* __restrict__ emb, const float* __restrict__ W, const float* __restrict__ bias,
    const void* __restrict__ inputs)
{
    table_gemm_body(emb, W, bias, g_pregates_enc, EE, inputs, 127 * TT);
}

// ---------------- persistent main kernel ----------------
// smem layout (static, ~39 KB)
struct MainSmem {
    __align__(16) float wsh[128][33];   // gates: w[col][k] (col = g*32+jj); fc reuses rows [n][k]
    __align__(16) float hsh[32][36];    // h[k][b] transposed chunk
    __align__(16) float gsh[128][34];   // gate pre-activation staging [col][b]
    int ssym[32];
};

__global__ __launch_bounds__(256, 1) void main_kernel(
    const void* __restrict__ inputs,
    const float* __restrict__ eWhh,
    const float* __restrict__ dWhh,
    const float* __restrict__ fcW,
    const float* __restrict__ fcb,
    float* __restrict__ out)
{
    __shared__ MainSmem smem;
    const int cta = blockIdx.x;
    const int tid = threadIdx.x;

    // ---- phase 0: zero encoder state ----
    if (cta == 0) {
        for (int i = tid; i < HH; i += 256) { g_he[0][i] = 0.0f; g_ce[i] = 0.0f; }
    }
    grid_bar();

    // ---- encoder: batch row 127 only, 128 steps ----
    {
        const int wid = tid >> 5, lane = tid & 31;
        const int j = cta * 8 + wid;
        const float* w = eWhh + (size_t)j * HH;
        for (int t = 0; t < TT; t++) {
            const float* hin = g_he[t & 1];
            float a0 = 0.f, a1 = 0.f, a2 = 0.f, a3 = 0.f;
#pragma unroll 4
            for (int k = lane; k < HH; k += 32) {
                float hv = hin[k];
                a0 += hv * w[k];
                a1 += hv * w[1024 * 1024 + k];
                a2 += hv * w[2 * 1024 * 1024 + k];
                a3 += hv * w[3 * 1024 * 1024 + k];
            }
#pragma unroll
            for (int o = 16; o; o >>= 1) {
                a0 += __shfl_xor_sync(0xffffffffu, a0, o);
                a1 += __shfl_xor_sync(0xffffffffu, a1, o);
                a2 += __shfl_xor_sync(0xffffffffu, a2, o);
                a3 += __shfl_xor_sync(0xffffffffu, a3, o);
            }
            if (lane == 0) {
                const float* pg = g_pregates_enc + (size_t)t * GG;
                float gi = a0 + pg[j];
                float gf = a1 + pg[HH + j];
                float gg = a2 + pg[2 * HH + j];
                float go = a3 + pg[3 * HH + j];
                float i_ = sigf(gi), f_ = sigf(gf), c_ = tanhf(gg), o_ = sigf(go);
                float c = f_ * g_ce[j] + i_ * c_;
                g_ce[j] = c;
                g_he[(t + 1) & 1][j] = o_ * tanhf(c);
            }
            grid_bar();
        }
    }

    // ---- decoder init ----
    {
        int base = cta * 1024 + tid * 4;
#pragma unroll
        for (int q = 0; q < 4; q++) {
            int k = tid * 4 + q;
            g_hd[0][base + q] = (cta == 127) ? g_he[0][k] : 0.0f;
            g_cd[base + q]    = (cta == 127) ? g_ce[k]    : 0.0f;
        }
    }
    grid_bar();

    // ---- decoder: 128 steps ----
    const int j0 = (cta & 31) * 32;          // gates j-tile / fc n-tile
    const int b0 = (cta >> 5) * 32;          // b-tile

    // gates inner-thread mapping
    const int bo = tid >> 6;                 // 0..3 (b-octet, warp-uniform)
    const int cg = tid & 63;                 // 0..63; cols cg and cg+64
    // chunk-load mapping (gates w)
    // fc mapping
    const int fn = tid & 31;                 // n within tile (lane)
    const int bq = tid >> 5;                 // 0..7 (b-quad, warp-uniform)

    float* gshp = &smem.gsh[0][0];
    float* wshp = &smem.wsh[0][0];
    float* hshp = &smem.hsh[0][0];

    for (int t = 0; t < TT; t++) {
        // ===== gates phase =====
        {
            const float* hin = g_hd[t & 1];
            float* hout = g_hd[(t + 1) & 1];

            // symbol preamble
            if (tid < 32) {
                int b = b0 + tid;
                int s;
                if (t == 0) {
                    s = read_idx(inputs, b * TT);
                } else {
                    unsigned long long key = g_amax[(t - 1) & 1][b];
                    s = (int)(~(unsigned)key & 1023u);
                    if ((cta & 31) == 0) out[OUT_SYM + b * TT + (t - 1)] = (float)s;
                }
                smem.ssym[tid] = s;
            }
            if (cta == 0 && tid < BB) g_amax[t & 1][tid] = 0ull;

            unsigned long long acc[4][2];
#pragma unroll
            for (int i = 0; i < 4; i++) { acc[i][0] = 0ull; acc[i][1] = 0ull; }

            // prefetch regs
            float4 wreg[4];
            float4 hreg;
            const int hb = tid >> 3;                 // 0..31
            const int hk = (tid & 7) << 2;           // 0..28
            {
                // chunk 0 loads
#pragma unroll
                for (int i = 0; i < 4; i++) {
                    int q = i * 256 + tid;
                    int c = q >> 3;
                    int ks = (q & 7) << 2;
                    int g = c >> 5, jj = c & 31;
                    wreg[i] = *(const float4*)(dWhh + ((size_t)(g * HH + j0 + jj)) * HH + ks);
                }
                hreg = *(const float4*)(hin + (size_t)(b0 + hb) * HH + hk);
            }

            const float* hbase = hshp + bo * 8;
            const float* w0p = wshp + cg * 33;
            const float* w1p = wshp + (cg + 64) * 33;

            for (int ch = 0; ch < 32; ch++) {
                __syncthreads();
                // store prefetched chunk to smem
#pragma unroll
                for (int i = 0; i < 4; i++) {
                    int q = i * 256 + tid;
                    int c = q >> 3;
                    int ks = (q & 7) << 2;
                    float* p = wshp + c * 33 + ks;
                    p[0] = wreg[i].x; p[1] = wreg[i].y; p[2] = wreg[i].z; p[3] = wreg[i].w;
                }
                {
                    float* p = hshp + hk * 36 + hb;
                    p[0] = hreg.x; p[36] = hreg.y; p[72] = hreg.z; p[108] = hreg.w;
                }
                // prefetch next chunk
                if (ch < 31) {
                    int k0 = (ch + 1) * 32;
#pragma unroll
                    for (int i = 0; i < 4; i++) {
                        int q = i * 256 + tid;
                        int c = q >> 3;
                        int ks = (q & 7) << 2;
                        int g = c >> 5, jj = c & 31;
                        wreg[i] = *(const float4*)(dWhh + ((size_t)(g * HH + j0 + jj)) * HH + k0 + ks);
                    }
                    hreg = *(const float4*)(hin + (size_t)(b0 + hb) * HH + k0 + hk);
                }
                __syncthreads();
                // compute 32 k from smem
#pragma unroll
                for (int k = 0; k < 32; k++) {
                    ulonglong2 h01 = *(const ulonglong2*)(hbase + k * 36);
                    ulonglong2 h23 = *(const ulonglong2*)(hbase + k * 36 + 4);
                    unsigned long long w0 = dupf(w0p[k]);
                    unsigned long long w1 = dupf(w1p[k]);
                    ffma2(acc[0][0], h01.x, w0); ffma2(acc[1][0], h01.y, w0);
                    ffma2(acc[2][0], h23.x, w0); ffma2(acc[3][0], h23.y, w0);
                    ffma2(acc[0][1], h01.x, w1); ffma2(acc[1][1], h01.y, w1);
                    ffma2(acc[2][1], h23.x, w1); ffma2(acc[3][1], h23.y, w1);
                }
            }

            // stage pre-activations to gsh[col][b]
            __syncthreads();
#pragma unroll
            for (int bp = 0; bp < 4; bp++) {
                *(unsigned long long*)(gshp + cg * 34 + bo * 8 + 2 * bp)        = acc[bp][0];
                *(unsigned long long*)(gshp + (cg + 64) * 34 + bo * 8 + 2 * bp) = acc[bp][1];
            }
            __syncthreads();

            // LSTM epilogue: thread: jj = tid&31, 4 b's
            {
                int jj = tid & 31;
                int bl = (tid >> 5) * 4;
                int jg = j0 + jj;
#pragma unroll
                for (int i = 0; i < 4; i++) {
                    int b = bl + i;
                    int s = smem.ssym[b];
                    const float* tb = g_dec_table + (size_t)s * GG + jg;
                    float gi = gshp[(0 * 32 + jj) * 34 + b] + tb[0];
                    float gf = gshp[(1 * 32 + jj) * 34 + b] + tb[HH];
                    float gg = gshp[(2 * 32 + jj) * 34 + b] + tb[2 * HH];
                    float go = gshp[(3 * 32 + jj) * 34 + b] + tb[3 * HH];
                    float i_ = sigf(gi), f_ = sigf(gf), c_ = tanhf(gg), o_ = sigf(go);
                    int off = (b0 + b) * HH + jg;
                    float c = f_ * g_cd[off] + i_ * c_;
                    g_cd[off] = c;
                    hout[off] = o_ * tanhf(c);
                }
            }
        }
        grid_bar();

        // ===== fc phase: logits = h @ fc_W^T + fc_b; write + argmax =====
        {
            const float* h = g_hd[(t + 1) & 1];
            unsigned long long a0 = 0ull, a1 = 0ull;

            float4 wreg;
            float4 hreg;
            const int wn = tid >> 3;                // 0..31
            const int wk = (tid & 7) << 2;
            const int hb = tid >> 3;
            const int hk = (tid & 7) << 2;
            wreg = *(const float4*)(fcW + (size_t)(j0 + wn) * HH + wk);
            hreg = *(const float4*)(h + (size_t)(b0 + hb) * HH + hk);

            const float* hbase = hshp + bq * 4;
            const float* wp = wshp + fn * 33;

            for (int ch = 0; ch < 32; ch++) {
                __syncthreads();
                {
                    float* p = wshp + wn * 33 + wk;
                    p[0] = wreg.x; p[1] = wreg.y; p[2] = wreg.z; p[3] = wreg.w;
                    float* ph = hshp + hk * 36 + hb;
                    ph[0] = hreg.x; ph[36] = hreg.y; ph[72] = hreg.z; ph[108] = hreg.w;
                }
                if (ch < 31) {
                    int k0 = (ch + 1) * 32;
                    wreg = *(const float4*)(fcW + (size_t)(j0 + wn) * HH + k0 + wk);
                    hreg = *(const float4*)(h + (size_t)(b0 + hb) * HH + k0 + hk);
                }
                __syncthreads();
#pragma unroll
                for (int k = 0; k < 32; k++) {
                    ulonglong2 hp = *(const ulonglong2*)(hbase + k * 36);
                    unsigned long long wd = dupf(wp[k]);
                    ffma2(a0, hp.x, wd);
                    ffma2(a1, hp.y, wd);
                }
            }

            int n = j0 + fn;
            float bias = fcb[n];
            float v[4] = { lo2(a0) + bias, hi2(a0) + bias, lo2(a1) + bias, hi2(a1) + bias };
#pragma unroll
            for (int i = 0; i < 4; i++) {
                int b = b0 + bq * 4 + i;
                out[OUT_DEC + (size_t)b * TT * HH + (size_t)t * HH + n] = v[i];
            }
#pragma unroll
            for (int i = 0; i < 4; i++) {
                unsigned long long key =
                    ((unsigned long long)monof(v[i]) << 32) | (unsigned)(~(unsigned)n);
#pragma unroll
                for (int off = 16; off; off >>= 1) {
                    unsigned long long o = __shfl_xor_sync(0xffffffffu, key, off);
                    if (o > key) key = o;
                }
                if (fn == 0) atomicMax(&g_amax[t & 1][b0 + bq * 4 + i], key);
            }
        }
        grid_bar();
    }

    // ---- final: symbols for t=127, hf/cf ----
    if ((cta & 31) == 0 && tid < 32) {
        int b = b0 + tid;
        unsigned long long key = g_amax[1][b];
        out[OUT_SYM + b * TT + 127] = (float)(~(unsigned)key & 1023u);
    }
    {
        int base = cta * 1024 + tid * 4;
#pragma unroll
        for (int q = 0; q < 4; q++) {
            out[OUT_HF + base + q] = g_hd[0][base + q];
            out[OUT_CF + base + q] = g_cd[base + q];
        }
    }
}

// ---------------- launcher ----------------
extern "C" void kernel_launch(void* const* d_in, const int* in_sizes, int n_in,
                              void* d_out, int out_size) {
    const void*  inputs = d_in[0];
    const float* emb    = (const float*)d_in[1];
    const float* eWih   = (const float*)d_in[2];
    const float* eWhh   = (const float*)d_in[3];
    const float* eb     = (const float*)d_in[4];
    const float* dWih   = (const float*)d_in[5];
    const float* dWhh   = (const float*)d_in[6];
    const float* db     = (const float*)d_in[7];
    const float* fcW    = (const float*)d_in[8];
    const float* fcb    = (const float*)d_in[9];
    float* out = (float*)d_out;

    detect_kernel<<<1, 32>>>(inputs);
    table_dec_kernel<<<dim3(64, 16), 256>>>(emb, dWih, db);
    table_pre_kernel<<<dim3(64, 2), 256>>>(emb, eWih, eb, inputs);
    main_kernel<<<NCTA, 256>>>(inputs, eWhh, dWhh, fcW, fcb, out);
}